// round 7
// baseline (speedup 1.0000x reference)
#include <cuda_runtime.h>
#include <cuda_fp16.h>
#include <cstdint>

#define NN 100000        // nodes
#define NE 1600000       // real edges
#define ET 1700000       // edges + self loops
#define DIM 128
#define NPAD 102400      // 100 blocks * 1024
#define LDSP 136         // padded smem row stride (floats)

// ---------------- scratch (device globals; no allocation allowed) -------------
__device__ __half g_hh[NN * DIM];   // h = x @ W  (current layer, fp16 for gather BW)
__device__ float  g_x1[NN * DIM];   // layer-1 output (relu'd, fp32)
__device__ float  g_als[NN * 8];    // per-node attn logits (src side)
__device__ float  g_ald[NN * 8];    // per-node attn logits (dst side)
__device__ int    g_cnt[NPAD];
__device__ int    g_off[NN + 1];
__device__ int    g_cur[NN];
__device__ int    g_csr [ET];
__device__ int    g_csr2[ET];       // sorted-by-src segments (deterministic)
__device__ int    g_bsum[128];

// ---------------- tf32 helpers (raw PTX; no mma.h) -----------------------------
__device__ __forceinline__ uint32_t f2tf32(float x) {
    uint32_t r;
    asm("cvt.rna.tf32.f32 %0, %1;" : "=r"(r) : "f"(x));
    return r;
}

__device__ __forceinline__ void mma_tf32(float& d0, float& d1, float& d2, float& d3,
                                         uint32_t a0, uint32_t a1, uint32_t a2, uint32_t a3,
                                         uint32_t b0, uint32_t b1) {
    asm volatile(
        "mma.sync.aligned.m16n8k8.row.col.f32.tf32.tf32.f32 "
        "{%0,%1,%2,%3}, {%4,%5,%6,%7}, {%8,%9}, {%0,%1,%2,%3};"
        : "+f"(d0), "+f"(d1), "+f"(d2), "+f"(d3)
        : "r"(a0), "r"(a1), "r"(a2), "r"(a3), "r"(b0), "r"(b1));
}

// ---------------- CSR build ---------------------------------------------------
__global__ void k_init_counts() {
    int i = blockIdx.x * 256 + threadIdx.x;
    if (i < NPAD) g_cnt[i] = (i < NN) ? 1 : 0;   // 1 = self loop
}

__global__ void k_hist(const int* __restrict__ ei) {
    int e = (blockIdx.x * 256 + threadIdx.x) * 4;
    if (e < NE) {
        int4 d = *(const int4*)&ei[NE + e];
        atomicAdd(&g_cnt[d.x], 1);
        atomicAdd(&g_cnt[d.y], 1);
        atomicAdd(&g_cnt[d.z], 1);
        atomicAdd(&g_cnt[d.w], 1);
    }
}

// pass 1: per-block exclusive scan (in place into g_cnt), block sums to g_bsum
__global__ void k_scan1() {
    __shared__ int ws[32];
    int tid = threadIdx.x;
    int i = blockIdx.x * 1024 + tid;
    int v = g_cnt[i];
    int x = v;
    #pragma unroll
    for (int d = 1; d < 32; d <<= 1) {
        int u = __shfl_up_sync(0xffffffffu, x, d);
        if ((tid & 31) >= d) x += u;
    }
    if ((tid & 31) == 31) ws[tid >> 5] = x;
    __syncthreads();
    if (tid < 32) {
        int w = ws[tid];
        #pragma unroll
        for (int d = 1; d < 32; d <<= 1) {
            int u = __shfl_up_sync(0xffffffffu, w, d);
            if (tid >= d) w += u;
        }
        ws[tid] = w;
    }
    __syncthreads();
    int woff = (tid >= 32) ? ws[(tid >> 5) - 1] : 0;
    g_cnt[i] = x - v + woff;                 // exclusive prefix within block
    if (tid == 1023) g_bsum[blockIdx.x] = x + woff;  // block total
}

// pass 2 (fused): each block sums bsum[0..blockIdx) itself, then emits g_off,
// the self-loop CSR entry, and the scatter cursor. Kills scan2 + selfloop.
__global__ void k_scan3f() {
    __shared__ int s_boff;
    int tid = threadIdx.x;
    if (tid < 32) {
        int s = 0;
        for (int j = tid; j < blockIdx.x; j += 32) s += g_bsum[j];
        #pragma unroll
        for (int d = 16; d; d >>= 1) s += __shfl_xor_sync(0xffffffffu, s, d);
        if (tid == 0) s_boff = s;
    }
    __syncthreads();
    int i = blockIdx.x * 1024 + tid;
    if (i < NN) {
        int o = g_cnt[i] + s_boff;
        g_off[i] = o;
        g_csr[o] = i;          // self loop first
        g_cur[i] = o + 1;
    }
    if (i == 0) g_off[NN] = ET;
}

__global__ void k_scatter(const int* __restrict__ ei) {
    int e = (blockIdx.x * 256 + threadIdx.x) * 4;
    if (e < NE) {
        int4 s = *(const int4*)&ei[e];
        int4 d = *(const int4*)&ei[NE + e];
        g_csr[atomicAdd(&g_cur[d.x], 1)] = s.x;
        g_csr[atomicAdd(&g_cur[d.y], 1)] = s.y;
        g_csr[atomicAdd(&g_cur[d.z], 1)] = s.z;
        g_csr[atomicAdd(&g_cur[d.w], 1)] = s.w;
    }
}

// deterministic per-segment rank sort by src value
__global__ void k_sortseg() {
    int n = blockIdx.x * 8 + (threadIdx.x >> 5);
    if (n >= NN) return;
    int lane = threadIdx.x & 31;
    int b = g_off[n];
    int len = g_off[n + 1] - b;
    for (int i = lane; i < len; i += 32) {
        int v = g_csr[b + i];
        int rank = 0;
        for (int j = 0; j < len; j++) {
            int u = g_csr[b + j];
            rank += (u < v) | ((u == v) & (j < i));
        }
        g_csr2[b + rank] = v;
    }
}

// ---------------- GEMM via raw mma.sync tf32 (3xTF32), fused logit epilogue ----
// Hh[nrows,128] (fp16) = X[nrows,128] @ W[128,128]; logits from fp32 tile.
// Block: 256 thr (8 warps), 128x128 tile; warp w owns rows [16w, 16w+16).
__global__ void k_gemm(const float* __restrict__ X, const float* __restrict__ W,
                       __half* __restrict__ Hh, int nrows,
                       const float* __restrict__ asrc, const float* __restrict__ adst) {
    extern __shared__ float sm[];
    float* Xs  = sm;                       // [128][LDSP] fp32 inputs (later: C staging)
    float* WhS = sm + 128 * LDSP;          // tf32-high of W (stored as float bits)
    float* WlS = WhS + 128 * LDSP;         // tf32-low  of W
    float* sA  = WlS + 128 * LDSP;         // asrc[128]
    float* sD  = sA + 128;                 // adst[128]
    int tid = threadIdx.x;
    int row0 = blockIdx.x * 128;

    if (tid < 128) { sA[tid] = asrc[tid]; sD[tid] = adst[tid]; }
    for (int i = tid; i < 128 * 128; i += 256) {
        int r = i >> 7, c = i & 127;
        Xs[r * LDSP + c] = (row0 + r < nrows) ? X[(row0 + r) * 128 + c] : 0.f;
        float w  = W[i];
        float wh = __uint_as_float(f2tf32(w));
        WhS[r * LDSP + c] = wh;
        WlS[r * LDSP + c] = __uint_as_float(f2tf32(w - wh));
    }
    __syncthreads();

    int warp = tid >> 5;
    int lane = tid & 31;
    int g = lane >> 2, t = lane & 3;
    int r0 = warp * 16;

    float acc[16][4];
    #pragma unroll
    for (int j = 0; j < 16; j++)
        #pragma unroll
        for (int q = 0; q < 4; q++) acc[j][q] = 0.f;

    const float* Arow0 = Xs + (r0 + g) * LDSP;
    const float* Arow1 = Xs + (r0 + g + 8) * LDSP;

    #pragma unroll 4
    for (int k = 0; k < 16; k++) {
        int k0 = k * 8;
        float f0 = Arow0[k0 + t];
        float f1 = Arow1[k0 + t];
        float f2 = Arow0[k0 + t + 4];
        float f3 = Arow1[k0 + t + 4];
        uint32_t ah0 = f2tf32(f0), ah1 = f2tf32(f1), ah2 = f2tf32(f2), ah3 = f2tf32(f3);
        uint32_t al0 = f2tf32(f0 - __uint_as_float(ah0));
        uint32_t al1 = f2tf32(f1 - __uint_as_float(ah1));
        uint32_t al2 = f2tf32(f2 - __uint_as_float(ah2));
        uint32_t al3 = f2tf32(f3 - __uint_as_float(ah3));
        const float* whr0 = WhS + (k0 + t) * LDSP + g;
        const float* whr1 = WhS + (k0 + t + 4) * LDSP + g;
        const float* wlr0 = WlS + (k0 + t) * LDSP + g;
        const float* wlr1 = WlS + (k0 + t + 4) * LDSP + g;
        #pragma unroll
        for (int j = 0; j < 16; j++) {
            int n0 = j * 8;
            uint32_t b0h = __float_as_uint(whr0[n0]);
            uint32_t b1h = __float_as_uint(whr1[n0]);
            uint32_t b0l = __float_as_uint(wlr0[n0]);
            uint32_t b1l = __float_as_uint(wlr1[n0]);
            mma_tf32(acc[j][0], acc[j][1], acc[j][2], acc[j][3],
                     ah0, ah1, ah2, ah3, b0h, b1h);
            mma_tf32(acc[j][0], acc[j][1], acc[j][2], acc[j][3],
                     al0, al1, al2, al3, b0h, b1h);
            mma_tf32(acc[j][0], acc[j][1], acc[j][2], acc[j][3],
                     ah0, ah1, ah2, ah3, b0l, b1l);
        }
    }

    // stage D through own smem strip (each warp owns rows [r0, r0+16) of Xs,
    // which only this warp read in the main loop -> no cross-warp hazard)
    float* Cs = Xs + r0 * LDSP;
    #pragma unroll
    for (int j = 0; j < 16; j++) {
        int n0 = j * 8;
        Cs[g * LDSP + n0 + 2 * t]           = acc[j][0];
        Cs[g * LDSP + n0 + 2 * t + 1]       = acc[j][1];
        Cs[(g + 8) * LDSP + n0 + 2 * t]     = acc[j][2];
        Cs[(g + 8) * LDSP + n0 + 2 * t + 1] = acc[j][3];
    }
    __syncwarp();

    // write Hh (fp16, guarded): 8 halves (16B) per lane per row-pair step
    #pragma unroll
    for (int r = 0; r < 16; r += 2) {
        int rr = r + (lane >> 4);
        int row = row0 + r0 + rr;
        if (row < nrows) {
            int cc = (lane & 15) * 8;
            float4 v0 = *(float4*)&Cs[rr * LDSP + cc];
            float4 v1 = *(float4*)&Cs[rr * LDSP + cc + 4];
            __half2 p0 = __floats2half2_rn(v0.x, v0.y);
            __half2 p1 = __floats2half2_rn(v0.z, v0.w);
            __half2 p2 = __floats2half2_rn(v1.x, v1.y);
            __half2 p3 = __floats2half2_rn(v1.z, v1.w);
            uint4 u;
            u.x = *(uint32_t*)&p0; u.y = *(uint32_t*)&p1;
            u.z = *(uint32_t*)&p2; u.w = *(uint32_t*)&p3;
            *(uint4*)&Hh[row * 128 + cc] = u;
        }
    }

    // fused attention logits: 2 lanes per row; each lane owns 64 cols = 4 heads
    {
        int r = lane >> 1;                 // 0..15
        int half = lane & 1;               // 0..1
        int row = row0 + r0 + r;
        if (row < nrows) {
            #pragma unroll
            for (int hh = 0; hh < 4; hh++) {
                int head = half * 4 + hh;
                int c0 = head * 16;
                float s = 0.f, p = 0.f;
                #pragma unroll
                for (int d = 0; d < 16; d += 4) {
                    float4 v = *(float4*)&Cs[r * LDSP + c0 + d];
                    float4 a = *(float4*)&sA[c0 + d];
                    float4 b = *(float4*)&sD[c0 + d];
                    s += v.x * a.x + v.y * a.y + v.z * a.z + v.w * a.w;
                    p += v.x * b.x + v.y * b.y + v.z * b.z + v.w * b.w;
                }
                g_als[row * 8 + head] = s;
                g_ald[row * 8 + head] = p;
            }
        }
    }
}

// ---------------- softmax-weighted aggregation (fp16 gathers, fp32 math) -------
__global__ void k_agg(const __half* __restrict__ Hh, const float* __restrict__ bias,
                      float* __restrict__ OUT, int do_relu) {
    int n = blockIdx.x * 8 + (threadIdx.x >> 5);
    if (n >= NN) return;
    int lane = threadIdx.x & 31;
    int b = g_off[n];
    int len = g_off[n + 1] - b;

    int head = lane >> 2;
    float aldh = g_ald[n * 8 + head];

    float4 acc = make_float4(0.f, 0.f, 0.f, 0.f);
    float ssum = 0.f;
    int i = 0;
    for (; i + 1 < len; i += 2) {
        int s0i = g_csr2[b + i];
        int s1i = g_csr2[b + i + 1];
        float al0 = g_als[s0i * 8 + head];
        float al1 = g_als[s1i * 8 + head];
        uint2 u0 = *(const uint2*)&Hh[s0i * DIM + lane * 4];
        uint2 u1 = *(const uint2*)&Hh[s1i * DIM + lane * 4];
        float e0 = al0 + aldh; e0 = (e0 > 0.f) ? e0 : 0.2f * e0;
        float e1 = al1 + aldh; e1 = (e1 > 0.f) ? e1 : 0.2f * e1;
        float w0 = __expf(e0);
        float w1 = __expf(e1);
        ssum += w0; ssum += w1;
        float2 f00 = __half22float2(*(__half2*)&u0.x);
        float2 f01 = __half22float2(*(__half2*)&u0.y);
        float2 f10 = __half22float2(*(__half2*)&u1.x);
        float2 f11 = __half22float2(*(__half2*)&u1.y);
        acc.x += f00.x * w0; acc.y += f00.y * w0; acc.z += f01.x * w0; acc.w += f01.y * w0;
        acc.x += f10.x * w1; acc.y += f10.y * w1; acc.z += f11.x * w1; acc.w += f11.y * w1;
    }
    if (i < len) {
        int s0i = g_csr2[b + i];
        float al0 = g_als[s0i * 8 + head];
        uint2 u0 = *(const uint2*)&Hh[s0i * DIM + lane * 4];
        float e0 = al0 + aldh; e0 = (e0 > 0.f) ? e0 : 0.2f * e0;
        float w0 = __expf(e0);
        ssum += w0;
        float2 f00 = __half22float2(*(__half2*)&u0.x);
        float2 f01 = __half22float2(*(__half2*)&u0.y);
        acc.x += f00.x * w0; acc.y += f00.y * w0; acc.z += f01.x * w0; acc.w += f01.y * w0;
    }

    float inv = 1.f / (ssum + 1e-16f);
    float4 b4 = *(const float4*)&bias[lane * 4];
    float4 o;
    o.x = acc.x * inv + b4.x;
    o.y = acc.y * inv + b4.y;
    o.z = acc.z * inv + b4.z;
    o.w = acc.w * inv + b4.w;
    if (do_relu) {
        o.x = fmaxf(o.x, 0.f); o.y = fmaxf(o.y, 0.f);
        o.z = fmaxf(o.z, 0.f); o.w = fmaxf(o.w, 0.f);
    }
    *(float4*)&OUT[n * DIM + lane * 4] = o;
}

// ---------------- treatment/control heads -------------------------------------
__global__ void k_heads(const float* __restrict__ Z, const int* __restrict__ tidx,
                        const int* __restrict__ cidx,
                        const float* __restrict__ wy1, const float* __restrict__ by1,
                        const float* __restrict__ wy0, const float* __restrict__ by0,
                        float* __restrict__ out) {
    int i = blockIdx.x * 8 + (threadIdx.x >> 5);
    if (i >= 40000) return;
    int lane = threadIdx.x & 31;
    int idx = (i < 20000) ? tidx[i] : cidx[i - 20000];
    float4 z  = *(const float4*)&Z[idx * DIM + lane * 4];
    float4 w1 = *(const float4*)&wy1[lane * 4];
    float4 w0 = *(const float4*)&wy0[lane * 4];
    float d1 = z.x * w1.x + z.y * w1.y + z.z * w1.z + z.w * w1.w;
    float d0 = z.x * w0.x + z.y * w0.y + z.z * w0.z + z.w * w0.w;
    #pragma unroll
    for (int d = 16; d; d >>= 1) {
        d1 += __shfl_xor_sync(0xffffffffu, d1, d);
        d0 += __shfl_xor_sync(0xffffffffu, d0, d);
    }
    if (lane == 0) {
        float v1 = d1 + by1[0]; v1 = (v1 > 0.f) ? v1 : 0.01f * v1;
        float v0 = d0 + by0[0]; v0 = (v0 > 0.f) ? v0 : 0.01f * v0;
        if (i < 20000) { out[i] = v1; out[20000 + i] = v0; }
        else { int j = i - 20000; out[40000 + j] = v0; out[60000 + j] = v1; }
    }
}

// ---------------- launch -------------------------------------------------------
extern "C" void kernel_launch(void* const* d_in, const int* in_sizes, int n_in,
                              void* d_out, int out_size) {
    const float* x   = (const float*)d_in[0];
    const int*   ei  = (const int*)  d_in[1];
    const int*   ti  = (const int*)  d_in[2];
    const int*   ci  = (const int*)  d_in[3];
    const float* W1  = (const float*)d_in[4];
    const float* as1 = (const float*)d_in[5];
    const float* ad1 = (const float*)d_in[6];
    const float* b1  = (const float*)d_in[7];
    const float* W2  = (const float*)d_in[8];
    const float* as2 = (const float*)d_in[9];
    const float* ad2 = (const float*)d_in[10];
    const float* b2  = (const float*)d_in[11];
    const float* wy1 = (const float*)d_in[12];
    const float* by1 = (const float*)d_in[13];
    const float* wy0 = (const float*)d_in[14];
    const float* by0 = (const float*)d_in[15];
    float* out = (float*)d_out;
    float* xZ2 = out + 80000;

    void *ph, *px1;
    cudaGetSymbolAddress(&ph,  g_hh);
    cudaGetSymbolAddress(&px1, g_x1);
    __half* hh = (__half*)ph;
    float*  x1 = (float*)px1;

    const int smem = (3 * 128 * LDSP + 256) * (int)sizeof(float);   // 209920 B
    cudaFuncSetAttribute(k_gemm, cudaFuncAttributeMaxDynamicSharedMemorySize, smem);

    // CSR build (6 launches)
    k_init_counts<<<(NPAD + 255) / 256, 256>>>();
    k_hist<<<(NE / 4 + 255) / 256, 256>>>(ei);
    k_scan1<<<NPAD / 1024, 1024>>>();
    k_scan3f<<<NPAD / 1024, 1024>>>();
    k_scatter<<<(NE / 4 + 255) / 256, 256>>>(ei);
    k_sortseg<<<(NN + 7) / 8, 256>>>();

    // layer 1 (GEMM fused with attention-logit epilogue, fp16 H)
    k_gemm<<<(NN + 127) / 128, 256, smem>>>(x, W1, hh, NN, as1, ad1);
    k_agg<<<(NN + 7) / 8, 256>>>(hh, b1, x1, 1);

    // layer 2 (output straight into d_out's xZ2 region)
    k_gemm<<<(NN + 127) / 128, 256, smem>>>(x1, W2, hh, NN, as2, ad2);
    k_agg<<<(NN + 7) / 8, 256>>>(hh, b2, xZ2, 0);

    // heads
    k_heads<<<(40000 + 7) / 8, 256>>>(xZ2, ti, ci, wy1, by1, wy0, by0, out);
}

// round 8
// speedup vs baseline: 1.4309x; 1.4309x over previous
#include <cuda_runtime.h>
#include <cstdint>

#define NN 100000        // nodes
#define NE 1600000       // real edges
#define ET 1700000       // edges + self loops
#define DIM 128
#define NPAD 102400      // 100 blocks * 1024
#define LDSP 136         // padded smem row stride (floats)

// ---------------- scratch (device globals; no allocation allowed) -------------
__device__ float g_h  [NN * DIM];   // h = x @ W  (current layer, fp32)
__device__ float g_x1 [NN * DIM];   // layer-1 output (relu'd)
__device__ float g_als[NN * 8];     // per-node attn logits (src side)
__device__ float g_ald[NN * 8];     // per-node attn logits (dst side)
__device__ int   g_cnt[NPAD];
__device__ int   g_off[NN + 1];
__device__ int   g_cur[NN];
__device__ int   g_csr [ET];
__device__ int   g_csr2[ET];        // sorted-by-src segments (deterministic)
__device__ int   g_bsum[128];

// ---------------- tf32 helpers (raw PTX; no mma.h) -----------------------------
__device__ __forceinline__ uint32_t f2tf32(float x) {
    uint32_t r;
    asm("cvt.rna.tf32.f32 %0, %1;" : "=r"(r) : "f"(x));
    return r;
}

__device__ __forceinline__ void mma_tf32(float& d0, float& d1, float& d2, float& d3,
                                         uint32_t a0, uint32_t a1, uint32_t a2, uint32_t a3,
                                         uint32_t b0, uint32_t b1) {
    asm volatile(
        "mma.sync.aligned.m16n8k8.row.col.f32.tf32.tf32.f32 "
        "{%0,%1,%2,%3}, {%4,%5,%6,%7}, {%8,%9}, {%0,%1,%2,%3};"
        : "+f"(d0), "+f"(d1), "+f"(d2), "+f"(d3)
        : "r"(a0), "r"(a1), "r"(a2), "r"(a3), "r"(b0), "r"(b1));
}

// ---------------- CSR build ---------------------------------------------------
__global__ void k_init_counts() {
    int i = blockIdx.x * 256 + threadIdx.x;
    if (i < NPAD) g_cnt[i] = (i < NN) ? 1 : 0;   // 1 = self loop
}

__global__ void k_hist(const int* __restrict__ ei) {
    int e = (blockIdx.x * 256 + threadIdx.x) * 4;
    if (e < NE) {
        int4 d = *(const int4*)&ei[NE + e];
        atomicAdd(&g_cnt[d.x], 1);
        atomicAdd(&g_cnt[d.y], 1);
        atomicAdd(&g_cnt[d.z], 1);
        atomicAdd(&g_cnt[d.w], 1);
    }
}

// pass 1: per-block exclusive scan (in place into g_cnt), block sums to g_bsum
__global__ void k_scan1() {
    __shared__ int ws[32];
    int tid = threadIdx.x;
    int i = blockIdx.x * 1024 + tid;
    int v = g_cnt[i];
    int x = v;
    #pragma unroll
    for (int d = 1; d < 32; d <<= 1) {
        int u = __shfl_up_sync(0xffffffffu, x, d);
        if ((tid & 31) >= d) x += u;
    }
    if ((tid & 31) == 31) ws[tid >> 5] = x;
    __syncthreads();
    if (tid < 32) {
        int w = ws[tid];
        #pragma unroll
        for (int d = 1; d < 32; d <<= 1) {
            int u = __shfl_up_sync(0xffffffffu, w, d);
            if (tid >= d) w += u;
        }
        ws[tid] = w;
    }
    __syncthreads();
    int woff = (tid >= 32) ? ws[(tid >> 5) - 1] : 0;
    g_cnt[i] = x - v + woff;                 // exclusive prefix within block
    if (tid == 1023) g_bsum[blockIdx.x] = x + woff;  // block total
}

// pass 2 (fused): each block sums bsum[0..blockIdx) itself, then emits g_off,
// the self-loop CSR entry, and the scatter cursor. Kills scan2 + selfloop.
__global__ void k_scan3f() {
    __shared__ int s_boff;
    int tid = threadIdx.x;
    if (tid < 32) {
        int s = 0;
        for (int j = tid; j < blockIdx.x; j += 32) s += g_bsum[j];
        #pragma unroll
        for (int d = 16; d; d >>= 1) s += __shfl_xor_sync(0xffffffffu, s, d);
        if (tid == 0) s_boff = s;
    }
    __syncthreads();
    int i = blockIdx.x * 1024 + tid;
    if (i < NN) {
        int o = g_cnt[i] + s_boff;
        g_off[i] = o;
        g_csr[o] = i;          // self loop first
        g_cur[i] = o + 1;
    }
    if (i == 0) g_off[NN] = ET;
}

__global__ void k_scatter(const int* __restrict__ ei) {
    int e = (blockIdx.x * 256 + threadIdx.x) * 4;
    if (e < NE) {
        int4 s = *(const int4*)&ei[e];
        int4 d = *(const int4*)&ei[NE + e];
        g_csr[atomicAdd(&g_cur[d.x], 1)] = s.x;
        g_csr[atomicAdd(&g_cur[d.y], 1)] = s.y;
        g_csr[atomicAdd(&g_cur[d.z], 1)] = s.z;
        g_csr[atomicAdd(&g_cur[d.w], 1)] = s.w;
    }
}

// deterministic per-segment rank sort by src value
__global__ void k_sortseg() {
    int n = blockIdx.x * 8 + (threadIdx.x >> 5);
    if (n >= NN) return;
    int lane = threadIdx.x & 31;
    int b = g_off[n];
    int len = g_off[n + 1] - b;
    for (int i = lane; i < len; i += 32) {
        int v = g_csr[b + i];
        int rank = 0;
        for (int j = 0; j < len; j++) {
            int u = g_csr[b + j];
            rank += (u < v) | ((u == v) & (j < i));
        }
        g_csr2[b + rank] = v;
    }
}

// ---------------- GEMM via raw mma.sync tf32 (3xTF32), fused logit epilogue ----
// H[nrows,128] = X[nrows,128] @ W[128,128], fp32-accurate (error ~2^-22).
// Block: 256 thr (8 warps), 128x128 tile; warp w owns rows [16w, 16w+16).
__global__ void k_gemm(const float* __restrict__ X, const float* __restrict__ W,
                       float* __restrict__ H, int nrows,
                       const float* __restrict__ asrc, const float* __restrict__ adst) {
    extern __shared__ float sm[];
    float* Xs  = sm;                       // [128][LDSP] fp32 inputs (later: C staging)
    float* WhS = sm + 128 * LDSP;          // tf32-high of W (stored as float bits)
    float* WlS = WhS + 128 * LDSP;         // tf32-low  of W
    float* sA  = WlS + 128 * LDSP;         // asrc[128]
    float* sD  = sA + 128;                 // adst[128]
    int tid = threadIdx.x;
    int row0 = blockIdx.x * 128;

    if (tid < 128) { sA[tid] = asrc[tid]; sD[tid] = adst[tid]; }
    // vectorized fill: 4096 float4s over 256 threads = 16 iterations
    for (int i = tid; i < 128 * 32; i += 256) {
        int r = i >> 5, c4 = (i & 31) * 4;
        float4 xv = make_float4(0.f, 0.f, 0.f, 0.f);
        if (row0 + r < nrows) xv = *(const float4*)&X[(row0 + r) * 128 + c4];
        *(float4*)&Xs[r * LDSP + c4] = xv;
        float4 wv = *(const float4*)&W[r * 128 + c4];
        float4 wh, wl;
        wh.x = __uint_as_float(f2tf32(wv.x)); wl.x = __uint_as_float(f2tf32(wv.x - wh.x));
        wh.y = __uint_as_float(f2tf32(wv.y)); wl.y = __uint_as_float(f2tf32(wv.y - wh.y));
        wh.z = __uint_as_float(f2tf32(wv.z)); wl.z = __uint_as_float(f2tf32(wv.z - wh.z));
        wh.w = __uint_as_float(f2tf32(wv.w)); wl.w = __uint_as_float(f2tf32(wv.w - wh.w));
        *(float4*)&WhS[r * LDSP + c4] = wh;
        *(float4*)&WlS[r * LDSP + c4] = wl;
    }
    __syncthreads();

    int warp = tid >> 5;
    int lane = tid & 31;
    int g = lane >> 2, t = lane & 3;
    int r0 = warp * 16;

    float acc[16][4];
    #pragma unroll
    for (int j = 0; j < 16; j++)
        #pragma unroll
        for (int q = 0; q < 4; q++) acc[j][q] = 0.f;

    const float* Arow0 = Xs + (r0 + g) * LDSP;
    const float* Arow1 = Xs + (r0 + g + 8) * LDSP;

    #pragma unroll 4
    for (int k = 0; k < 16; k++) {
        int k0 = k * 8;
        float f0 = Arow0[k0 + t];
        float f1 = Arow1[k0 + t];
        float f2 = Arow0[k0 + t + 4];
        float f3 = Arow1[k0 + t + 4];
        uint32_t ah0 = f2tf32(f0), ah1 = f2tf32(f1), ah2 = f2tf32(f2), ah3 = f2tf32(f3);
        uint32_t al0 = f2tf32(f0 - __uint_as_float(ah0));
        uint32_t al1 = f2tf32(f1 - __uint_as_float(ah1));
        uint32_t al2 = f2tf32(f2 - __uint_as_float(ah2));
        uint32_t al3 = f2tf32(f3 - __uint_as_float(ah3));
        const float* whr0 = WhS + (k0 + t) * LDSP + g;
        const float* whr1 = WhS + (k0 + t + 4) * LDSP + g;
        const float* wlr0 = WlS + (k0 + t) * LDSP + g;
        const float* wlr1 = WlS + (k0 + t + 4) * LDSP + g;
        #pragma unroll
        for (int j = 0; j < 16; j++) {
            int n0 = j * 8;
            uint32_t b0h = __float_as_uint(whr0[n0]);
            uint32_t b1h = __float_as_uint(whr1[n0]);
            uint32_t b0l = __float_as_uint(wlr0[n0]);
            uint32_t b1l = __float_as_uint(wlr1[n0]);
            mma_tf32(acc[j][0], acc[j][1], acc[j][2], acc[j][3],
                     ah0, ah1, ah2, ah3, b0h, b1h);
            mma_tf32(acc[j][0], acc[j][1], acc[j][2], acc[j][3],
                     al0, al1, al2, al3, b0h, b1h);
            mma_tf32(acc[j][0], acc[j][1], acc[j][2], acc[j][3],
                     ah0, ah1, ah2, ah3, b0l, b1l);
        }
    }

    // stage D through own smem strip (each warp owns rows [r0, r0+16) of Xs,
    // which only this warp read in the main loop -> no cross-warp hazard)
    float* Cs = Xs + r0 * LDSP;
    #pragma unroll
    for (int j = 0; j < 16; j++) {
        int n0 = j * 8;
        Cs[g * LDSP + n0 + 2 * t]           = acc[j][0];
        Cs[g * LDSP + n0 + 2 * t + 1]       = acc[j][1];
        Cs[(g + 8) * LDSP + n0 + 2 * t]     = acc[j][2];
        Cs[(g + 8) * LDSP + n0 + 2 * t + 1] = acc[j][3];
    }
    __syncwarp();

    // write H (fp32, guarded)
    #pragma unroll
    for (int r = 0; r < 16; r += 2) {
        int rr = r + (lane >> 4);
        int row = row0 + r0 + rr;
        if (row < nrows) {
            int cc = (lane & 15) * 8;
            float4 v0 = *(float4*)&Cs[rr * LDSP + cc];
            float4 v1 = *(float4*)&Cs[rr * LDSP + cc + 4];
            *(float4*)&H[row * 128 + cc]     = v0;
            *(float4*)&H[row * 128 + cc + 4] = v1;
        }
    }

    // fused attention logits: 2 lanes per row; each lane owns 64 cols = 4 heads
    {
        int r = lane >> 1;                 // 0..15
        int half = lane & 1;               // 0..1
        int row = row0 + r0 + r;
        if (row < nrows) {
            #pragma unroll
            for (int hh = 0; hh < 4; hh++) {
                int head = half * 4 + hh;
                int c0 = head * 16;
                float s = 0.f, p = 0.f;
                #pragma unroll
                for (int d = 0; d < 16; d += 4) {
                    float4 v = *(float4*)&Cs[r * LDSP + c0 + d];
                    float4 a = *(float4*)&sA[c0 + d];
                    float4 b = *(float4*)&sD[c0 + d];
                    s += v.x * a.x + v.y * a.y + v.z * a.z + v.w * a.w;
                    p += v.x * b.x + v.y * b.y + v.z * b.z + v.w * b.w;
                }
                g_als[row * 8 + head] = s;
                g_ald[row * 8 + head] = p;
            }
        }
    }
}

// ---------------- softmax-weighted aggregation (fp32; no max pass) -------------
__global__ void k_agg(const float* __restrict__ H, const float* __restrict__ bias,
                      float* __restrict__ OUT, int do_relu) {
    int n = blockIdx.x * 8 + (threadIdx.x >> 5);
    if (n >= NN) return;
    int lane = threadIdx.x & 31;
    int b = g_off[n];
    int len = g_off[n + 1] - b;

    int head = lane >> 2;
    float aldh = g_ald[n * 8 + head];

    float4 acc = make_float4(0.f, 0.f, 0.f, 0.f);
    float ssum = 0.f;
    int i = 0;
    for (; i + 3 < len; i += 4) {
        int s0i = g_csr2[b + i];
        int s1i = g_csr2[b + i + 1];
        int s2i = g_csr2[b + i + 2];
        int s3i = g_csr2[b + i + 3];
        float al0 = g_als[s0i * 8 + head];
        float al1 = g_als[s1i * 8 + head];
        float al2 = g_als[s2i * 8 + head];
        float al3 = g_als[s3i * 8 + head];
        float4 h0 = *(const float4*)&H[s0i * DIM + lane * 4];
        float4 h1 = *(const float4*)&H[s1i * DIM + lane * 4];
        float4 h2 = *(const float4*)&H[s2i * DIM + lane * 4];
        float4 h3 = *(const float4*)&H[s3i * DIM + lane * 4];
        float e0 = al0 + aldh; e0 = (e0 > 0.f) ? e0 : 0.2f * e0;
        float e1 = al1 + aldh; e1 = (e1 > 0.f) ? e1 : 0.2f * e1;
        float e2 = al2 + aldh; e2 = (e2 > 0.f) ? e2 : 0.2f * e2;
        float e3 = al3 + aldh; e3 = (e3 > 0.f) ? e3 : 0.2f * e3;
        float w0 = __expf(e0), w1 = __expf(e1), w2 = __expf(e2), w3 = __expf(e3);
        ssum += w0; ssum += w1; ssum += w2; ssum += w3;
        acc.x += h0.x * w0; acc.y += h0.y * w0; acc.z += h0.z * w0; acc.w += h0.w * w0;
        acc.x += h1.x * w1; acc.y += h1.y * w1; acc.z += h1.z * w1; acc.w += h1.w * w1;
        acc.x += h2.x * w2; acc.y += h2.y * w2; acc.z += h2.z * w2; acc.w += h2.w * w2;
        acc.x += h3.x * w3; acc.y += h3.y * w3; acc.z += h3.z * w3; acc.w += h3.w * w3;
    }
    for (; i < len; i++) {
        int s0i = g_csr2[b + i];
        float al0 = g_als[s0i * 8 + head];
        float4 h0 = *(const float4*)&H[s0i * DIM + lane * 4];
        float e0 = al0 + aldh; e0 = (e0 > 0.f) ? e0 : 0.2f * e0;
        float w0 = __expf(e0);
        ssum += w0;
        acc.x += h0.x * w0; acc.y += h0.y * w0; acc.z += h0.z * w0; acc.w += h0.w * w0;
    }

    float inv = 1.f / (ssum + 1e-16f);
    float4 b4 = *(const float4*)&bias[lane * 4];
    float4 o;
    o.x = acc.x * inv + b4.x;
    o.y = acc.y * inv + b4.y;
    o.z = acc.z * inv + b4.z;
    o.w = acc.w * inv + b4.w;
    if (do_relu) {
        o.x = fmaxf(o.x, 0.f); o.y = fmaxf(o.y, 0.f);
        o.z = fmaxf(o.z, 0.f); o.w = fmaxf(o.w, 0.f);
    }
    *(float4*)&OUT[n * DIM + lane * 4] = o;
}

// ---------------- treatment/control heads -------------------------------------
__global__ void k_heads(const float* __restrict__ Z, const int* __restrict__ tidx,
                        const int* __restrict__ cidx,
                        const float* __restrict__ wy1, const float* __restrict__ by1,
                        const float* __restrict__ wy0, const float* __restrict__ by0,
                        float* __restrict__ out) {
    int i = blockIdx.x * 8 + (threadIdx.x >> 5);
    if (i >= 40000) return;
    int lane = threadIdx.x & 31;
    int idx = (i < 20000) ? tidx[i] : cidx[i - 20000];
    float4 z  = *(const float4*)&Z[idx * DIM + lane * 4];
    float4 w1 = *(const float4*)&wy1[lane * 4];
    float4 w0 = *(const float4*)&wy0[lane * 4];
    float d1 = z.x * w1.x + z.y * w1.y + z.z * w1.z + z.w * w1.w;
    float d0 = z.x * w0.x + z.y * w0.y + z.z * w0.z + z.w * w0.w;
    #pragma unroll
    for (int d = 16; d; d >>= 1) {
        d1 += __shfl_xor_sync(0xffffffffu, d1, d);
        d0 += __shfl_xor_sync(0xffffffffu, d0, d);
    }
    if (lane == 0) {
        float v1 = d1 + by1[0]; v1 = (v1 > 0.f) ? v1 : 0.01f * v1;
        float v0 = d0 + by0[0]; v0 = (v0 > 0.f) ? v0 : 0.01f * v0;
        if (i < 20000) { out[i] = v1; out[20000 + i] = v0; }
        else { int j = i - 20000; out[40000 + j] = v0; out[60000 + j] = v1; }
    }
}

// ---------------- launch -------------------------------------------------------
extern "C" void kernel_launch(void* const* d_in, const int* in_sizes, int n_in,
                              void* d_out, int out_size) {
    const float* x   = (const float*)d_in[0];
    const int*   ei  = (const int*)  d_in[1];
    const int*   ti  = (const int*)  d_in[2];
    const int*   ci  = (const int*)  d_in[3];
    const float* W1  = (const float*)d_in[4];
    const float* as1 = (const float*)d_in[5];
    const float* ad1 = (const float*)d_in[6];
    const float* b1  = (const float*)d_in[7];
    const float* W2  = (const float*)d_in[8];
    const float* as2 = (const float*)d_in[9];
    const float* ad2 = (const float*)d_in[10];
    const float* b2  = (const float*)d_in[11];
    const float* wy1 = (const float*)d_in[12];
    const float* by1 = (const float*)d_in[13];
    const float* wy0 = (const float*)d_in[14];
    const float* by0 = (const float*)d_in[15];
    float* out = (float*)d_out;
    float* xZ2 = out + 80000;

    void *ph, *px1;
    cudaGetSymbolAddress(&ph,  g_h);
    cudaGetSymbolAddress(&px1, g_x1);
    float* h  = (float*)ph;
    float* x1 = (float*)px1;

    const int smem = (3 * 128 * LDSP + 256) * (int)sizeof(float);   // 209920 B
    cudaFuncSetAttribute(k_gemm, cudaFuncAttributeMaxDynamicSharedMemorySize, smem);

    // CSR build (6 launches)
    k_init_counts<<<(NPAD + 255) / 256, 256>>>();
    k_hist<<<(NE / 4 + 255) / 256, 256>>>(ei);
    k_scan1<<<NPAD / 1024, 1024>>>();
    k_scan3f<<<NPAD / 1024, 1024>>>();
    k_scatter<<<(NE / 4 + 255) / 256, 256>>>(ei);
    k_sortseg<<<(NN + 7) / 8, 256>>>();

    // layer 1 (GEMM fused with attention-logit epilogue)
    k_gemm<<<(NN + 127) / 128, 256, smem>>>(x, W1, h, NN, as1, ad1);
    k_agg<<<(NN + 7) / 8, 256>>>(h, b1, x1, 1);

    // layer 2 (output straight into d_out's xZ2 region)
    k_gemm<<<(NN + 127) / 128, 256, smem>>>(x1, W2, h, NN, as2, ad2);
    k_agg<<<(NN + 7) / 8, 256>>>(h, b2, xZ2, 0);

    // heads
    k_heads<<<(40000 + 7) / 8, 256>>>(xZ2, ti, ci, wy1, by1, wy0, by0, out);
}

// round 9
// speedup vs baseline: 1.4754x; 1.0311x over previous
#include <cuda_runtime.h>
#include <cstdint>

#define NN 100000        // nodes
#define NE 1600000       // real edges
#define ET 1700000       // edges + self loops
#define DIM 128
#define NPAD 102400      // 100 blocks * 1024
#define LDSP 136         // padded smem row stride (floats)

// ---------------- scratch (device globals; no allocation allowed) -------------
__device__ float g_h  [NN * DIM];   // h = x @ W  (current layer, fp32)
__device__ float g_x1 [NN * DIM];   // layer-1 output (relu'd)
__device__ float g_als[NN * 8];     // per-node attn logits (src side)
__device__ float g_ald[NN * 8];     // per-node attn logits (dst side)
__device__ int   g_cnt[NPAD];       // zero at module load; restored to zero each call
__device__ int   g_off[NN + 1];
__device__ int   g_cur[NN];
__device__ int   g_csr [ET];
__device__ int   g_csr2[ET];        // sorted-by-src segments (deterministic)
__device__ int   g_bsum[128];

// ---------------- tf32 helpers (raw PTX; no mma.h) -----------------------------
__device__ __forceinline__ uint32_t f2tf32(float x) {
    uint32_t r;
    asm("cvt.rna.tf32.f32 %0, %1;" : "=r"(r) : "f"(x));
    return r;
}

__device__ __forceinline__ void mma_tf32(float& d0, float& d1, float& d2, float& d3,
                                         uint32_t a0, uint32_t a1, uint32_t a2, uint32_t a3,
                                         uint32_t b0, uint32_t b1) {
    asm volatile(
        "mma.sync.aligned.m16n8k8.row.col.f32.tf32.tf32.f32 "
        "{%0,%1,%2,%3}, {%4,%5,%6,%7}, {%8,%9}, {%0,%1,%2,%3};"
        : "+f"(d0), "+f"(d1), "+f"(d2), "+f"(d3)
        : "r"(a0), "r"(a1), "r"(a2), "r"(a3), "r"(b0), "r"(b1));
}

// ---------------- CSR build ---------------------------------------------------
// g_cnt holds ONLY real-edge counts (self loops are analytic: off[i] = pfx[i] + i).
// g_cnt must be all-zero on entry; k_scan3f restores it to zero after consuming.
__global__ void k_hist(const int* __restrict__ ei) {
    int e = (blockIdx.x * 256 + threadIdx.x) * 4;
    if (e < NE) {
        int4 d = *(const int4*)&ei[NE + e];
        atomicAdd(&g_cnt[d.x], 1);
        atomicAdd(&g_cnt[d.y], 1);
        atomicAdd(&g_cnt[d.z], 1);
        atomicAdd(&g_cnt[d.w], 1);
    }
}

// pass 1: per-block exclusive scan (in place into g_cnt), block sums to g_bsum
__global__ void k_scan1() {
    __shared__ int ws[32];
    int tid = threadIdx.x;
    int i = blockIdx.x * 1024 + tid;
    int v = g_cnt[i];
    int x = v;
    #pragma unroll
    for (int d = 1; d < 32; d <<= 1) {
        int u = __shfl_up_sync(0xffffffffu, x, d);
        if ((tid & 31) >= d) x += u;
    }
    if ((tid & 31) == 31) ws[tid >> 5] = x;
    __syncthreads();
    if (tid < 32) {
        int w = ws[tid];
        #pragma unroll
        for (int d = 1; d < 32; d <<= 1) {
            int u = __shfl_up_sync(0xffffffffu, w, d);
            if (tid >= d) w += u;
        }
        ws[tid] = w;
    }
    __syncthreads();
    int woff = (tid >= 32) ? ws[(tid >> 5) - 1] : 0;
    g_cnt[i] = x - v + woff;                 // exclusive prefix within block
    if (tid == 1023) g_bsum[blockIdx.x] = x + woff;  // block total
}

// pass 2 (fused): block-offset reduce + emit g_off (with analytic +i self loops),
// self-loop CSR entry, scatter cursor; then restore g_cnt to zero for next call.
__global__ void k_scan3f() {
    __shared__ int s_boff;
    int tid = threadIdx.x;
    if (tid < 32) {
        int s = 0;
        for (int j = tid; j < blockIdx.x; j += 32) s += g_bsum[j];
        #pragma unroll
        for (int d = 16; d; d >>= 1) s += __shfl_xor_sync(0xffffffffu, s, d);
        if (tid == 0) s_boff = s;
    }
    __syncthreads();
    int i = blockIdx.x * 1024 + tid;
    if (i < NN) {
        int o = g_cnt[i] + s_boff + i;       // +i = self loops of nodes before i
        g_off[i] = o;
        g_csr[o] = i;          // self loop first
        g_cur[i] = o + 1;
    }
    g_cnt[i] = 0;                            // restore init state (full NPAD range)
    if (i == 0) g_off[NN] = ET;
}

__global__ void k_scatter(const int* __restrict__ ei) {
    int e = (blockIdx.x * 256 + threadIdx.x) * 4;
    if (e < NE) {
        int4 s = *(const int4*)&ei[e];
        int4 d = *(const int4*)&ei[NE + e];
        g_csr[atomicAdd(&g_cur[d.x], 1)] = s.x;
        g_csr[atomicAdd(&g_cur[d.y], 1)] = s.y;
        g_csr[atomicAdd(&g_cur[d.z], 1)] = s.z;
        g_csr[atomicAdd(&g_cur[d.w], 1)] = s.w;
    }
}

// deterministic per-segment rank sort by src value (smem-staged fast path)
__global__ void k_sortseg() {
    __shared__ int seg[8][128];
    int w = threadIdx.x >> 5;
    int n = blockIdx.x * 8 + w;
    if (n >= NN) return;
    int lane = threadIdx.x & 31;
    int b = g_off[n];
    int len = g_off[n + 1] - b;
    if (len <= 128) {
        for (int i = lane; i < len; i += 32) seg[w][i] = g_csr[b + i];
        __syncwarp();
        for (int i = lane; i < len; i += 32) {
            int v = seg[w][i];
            int rank = 0;
            for (int j = 0; j < len; j++) {
                int u = seg[w][j];
                rank += (u < v) | ((u == v) & (j < i));
            }
            g_csr2[b + rank] = v;
        }
    } else {
        for (int i = lane; i < len; i += 32) {
            int v = g_csr[b + i];
            int rank = 0;
            for (int j = 0; j < len; j++) {
                int u = g_csr[b + j];
                rank += (u < v) | ((u == v) & (j < i));
            }
            g_csr2[b + rank] = v;
        }
    }
}

// ---------------- GEMM via raw mma.sync tf32 (3xTF32), fused logit epilogue ----
// H[nrows,128] = X[nrows,128] @ W[128,128], fp32-accurate (error ~2^-22).
// Block: 256 thr (8 warps), 128x128 tile; warp w owns rows [16w, 16w+16).
__global__ void k_gemm(const float* __restrict__ X, const float* __restrict__ W,
                       float* __restrict__ H, int nrows,
                       const float* __restrict__ asrc, const float* __restrict__ adst) {
    extern __shared__ float sm[];
    float* Xs  = sm;                       // [128][LDSP] fp32 inputs (later: C staging)
    float* WhS = sm + 128 * LDSP;          // tf32-high of W (stored as float bits)
    float* WlS = WhS + 128 * LDSP;         // tf32-low  of W
    float* sA  = WlS + 128 * LDSP;         // asrc[128]
    float* sD  = sA + 128;                 // adst[128]
    int tid = threadIdx.x;
    int row0 = blockIdx.x * 128;

    if (tid < 128) { sA[tid] = asrc[tid]; sD[tid] = adst[tid]; }
    // vectorized fill: 4096 float4s over 256 threads = 16 iterations
    for (int i = tid; i < 128 * 32; i += 256) {
        int r = i >> 5, c4 = (i & 31) * 4;
        float4 xv = make_float4(0.f, 0.f, 0.f, 0.f);
        if (row0 + r < nrows) xv = *(const float4*)&X[(row0 + r) * 128 + c4];
        *(float4*)&Xs[r * LDSP + c4] = xv;
        float4 wv = *(const float4*)&W[r * 128 + c4];
        float4 wh, wl;
        wh.x = __uint_as_float(f2tf32(wv.x)); wl.x = __uint_as_float(f2tf32(wv.x - wh.x));
        wh.y = __uint_as_float(f2tf32(wv.y)); wl.y = __uint_as_float(f2tf32(wv.y - wh.y));
        wh.z = __uint_as_float(f2tf32(wv.z)); wl.z = __uint_as_float(f2tf32(wv.z - wh.z));
        wh.w = __uint_as_float(f2tf32(wv.w)); wl.w = __uint_as_float(f2tf32(wv.w - wh.w));
        *(float4*)&WhS[r * LDSP + c4] = wh;
        *(float4*)&WlS[r * LDSP + c4] = wl;
    }
    __syncthreads();

    int warp = tid >> 5;
    int lane = tid & 31;
    int g = lane >> 2, t = lane & 3;
    int r0 = warp * 16;

    float acc[16][4];
    #pragma unroll
    for (int j = 0; j < 16; j++)
        #pragma unroll
        for (int q = 0; q < 4; q++) acc[j][q] = 0.f;

    const float* Arow0 = Xs + (r0 + g) * LDSP;
    const float* Arow1 = Xs + (r0 + g + 8) * LDSP;

    #pragma unroll 4
    for (int k = 0; k < 16; k++) {
        int k0 = k * 8;
        float f0 = Arow0[k0 + t];
        float f1 = Arow1[k0 + t];
        float f2 = Arow0[k0 + t + 4];
        float f3 = Arow1[k0 + t + 4];
        uint32_t ah0 = f2tf32(f0), ah1 = f2tf32(f1), ah2 = f2tf32(f2), ah3 = f2tf32(f3);
        uint32_t al0 = f2tf32(f0 - __uint_as_float(ah0));
        uint32_t al1 = f2tf32(f1 - __uint_as_float(ah1));
        uint32_t al2 = f2tf32(f2 - __uint_as_float(ah2));
        uint32_t al3 = f2tf32(f3 - __uint_as_float(ah3));
        const float* whr0 = WhS + (k0 + t) * LDSP + g;
        const float* whr1 = WhS + (k0 + t + 4) * LDSP + g;
        const float* wlr0 = WlS + (k0 + t) * LDSP + g;
        const float* wlr1 = WlS + (k0 + t + 4) * LDSP + g;
        #pragma unroll
        for (int j = 0; j < 16; j++) {
            int n0 = j * 8;
            uint32_t b0h = __float_as_uint(whr0[n0]);
            uint32_t b1h = __float_as_uint(whr1[n0]);
            uint32_t b0l = __float_as_uint(wlr0[n0]);
            uint32_t b1l = __float_as_uint(wlr1[n0]);
            mma_tf32(acc[j][0], acc[j][1], acc[j][2], acc[j][3],
                     ah0, ah1, ah2, ah3, b0h, b1h);
            mma_tf32(acc[j][0], acc[j][1], acc[j][2], acc[j][3],
                     al0, al1, al2, al3, b0h, b1h);
            mma_tf32(acc[j][0], acc[j][1], acc[j][2], acc[j][3],
                     ah0, ah1, ah2, ah3, b0l, b1l);
        }
    }

    // stage D through own smem strip (each warp owns rows [r0, r0+16) of Xs,
    // which only this warp read in the main loop -> no cross-warp hazard)
    float* Cs = Xs + r0 * LDSP;
    #pragma unroll
    for (int j = 0; j < 16; j++) {
        int n0 = j * 8;
        Cs[g * LDSP + n0 + 2 * t]           = acc[j][0];
        Cs[g * LDSP + n0 + 2 * t + 1]       = acc[j][1];
        Cs[(g + 8) * LDSP + n0 + 2 * t]     = acc[j][2];
        Cs[(g + 8) * LDSP + n0 + 2 * t + 1] = acc[j][3];
    }
    __syncwarp();

    // write H (fp32, guarded)
    #pragma unroll
    for (int r = 0; r < 16; r += 2) {
        int rr = r + (lane >> 4);
        int row = row0 + r0 + rr;
        if (row < nrows) {
            int cc = (lane & 15) * 8;
            float4 v0 = *(float4*)&Cs[rr * LDSP + cc];
            float4 v1 = *(float4*)&Cs[rr * LDSP + cc + 4];
            *(float4*)&H[row * 128 + cc]     = v0;
            *(float4*)&H[row * 128 + cc + 4] = v1;
        }
    }

    // fused attention logits: 2 lanes per row; each lane owns 64 cols = 4 heads
    {
        int r = lane >> 1;                 // 0..15
        int half = lane & 1;               // 0..1
        int row = row0 + r0 + r;
        if (row < nrows) {
            #pragma unroll
            for (int hh = 0; hh < 4; hh++) {
                int head = half * 4 + hh;
                int c0 = head * 16;
                float s = 0.f, p = 0.f;
                #pragma unroll
                for (int d = 0; d < 16; d += 4) {
                    float4 v = *(float4*)&Cs[r * LDSP + c0 + d];
                    float4 a = *(float4*)&sA[c0 + d];
                    float4 b = *(float4*)&sD[c0 + d];
                    s += v.x * a.x + v.y * a.y + v.z * a.z + v.w * a.w;
                    p += v.x * b.x + v.y * b.y + v.z * b.z + v.w * b.w;
                }
                g_als[row * 8 + head] = s;
                g_ald[row * 8 + head] = p;
            }
        }
    }
}

// ---------------- softmax-weighted aggregation (fp32; no max pass) -------------
__global__ void k_agg(const float* __restrict__ H, const float* __restrict__ bias,
                      float* __restrict__ OUT, int do_relu) {
    int n = blockIdx.x * 8 + (threadIdx.x >> 5);
    if (n >= NN) return;
    int lane = threadIdx.x & 31;
    int b = g_off[n];
    int len = g_off[n + 1] - b;

    int head = lane >> 2;
    float aldh = g_ald[n * 8 + head];

    float4 acc = make_float4(0.f, 0.f, 0.f, 0.f);
    float ssum = 0.f;
    int i = 0;
    for (; i + 3 < len; i += 4) {
        int s0i = g_csr2[b + i];
        int s1i = g_csr2[b + i + 1];
        int s2i = g_csr2[b + i + 2];
        int s3i = g_csr2[b + i + 3];
        float al0 = g_als[s0i * 8 + head];
        float al1 = g_als[s1i * 8 + head];
        float al2 = g_als[s2i * 8 + head];
        float al3 = g_als[s3i * 8 + head];
        float4 h0 = *(const float4*)&H[s0i * DIM + lane * 4];
        float4 h1 = *(const float4*)&H[s1i * DIM + lane * 4];
        float4 h2 = *(const float4*)&H[s2i * DIM + lane * 4];
        float4 h3 = *(const float4*)&H[s3i * DIM + lane * 4];
        float e0 = al0 + aldh; e0 = (e0 > 0.f) ? e0 : 0.2f * e0;
        float e1 = al1 + aldh; e1 = (e1 > 0.f) ? e1 : 0.2f * e1;
        float e2 = al2 + aldh; e2 = (e2 > 0.f) ? e2 : 0.2f * e2;
        float e3 = al3 + aldh; e3 = (e3 > 0.f) ? e3 : 0.2f * e3;
        float w0 = __expf(e0), w1 = __expf(e1), w2 = __expf(e2), w3 = __expf(e3);
        ssum += w0; ssum += w1; ssum += w2; ssum += w3;
        acc.x += h0.x * w0; acc.y += h0.y * w0; acc.z += h0.z * w0; acc.w += h0.w * w0;
        acc.x += h1.x * w1; acc.y += h1.y * w1; acc.z += h1.z * w1; acc.w += h1.w * w1;
        acc.x += h2.x * w2; acc.y += h2.y * w2; acc.z += h2.z * w2; acc.w += h2.w * w2;
        acc.x += h3.x * w3; acc.y += h3.y * w3; acc.z += h3.z * w3; acc.w += h3.w * w3;
    }
    for (; i < len; i++) {
        int s0i = g_csr2[b + i];
        float al0 = g_als[s0i * 8 + head];
        float4 h0 = *(const float4*)&H[s0i * DIM + lane * 4];
        float e0 = al0 + aldh; e0 = (e0 > 0.f) ? e0 : 0.2f * e0;
        float w0 = __expf(e0);
        ssum += w0;
        acc.x += h0.x * w0; acc.y += h0.y * w0; acc.z += h0.z * w0; acc.w += h0.w * w0;
    }

    float inv = 1.f / (ssum + 1e-16f);
    float4 b4 = *(const float4*)&bias[lane * 4];
    float4 o;
    o.x = acc.x * inv + b4.x;
    o.y = acc.y * inv + b4.y;
    o.z = acc.z * inv + b4.z;
    o.w = acc.w * inv + b4.w;
    if (do_relu) {
        o.x = fmaxf(o.x, 0.f); o.y = fmaxf(o.y, 0.f);
        o.z = fmaxf(o.z, 0.f); o.w = fmaxf(o.w, 0.f);
    }
    *(float4*)&OUT[n * DIM + lane * 4] = o;
}

// ---------------- treatment/control heads -------------------------------------
__global__ void k_heads(const float* __restrict__ Z, const int* __restrict__ tidx,
                        const int* __restrict__ cidx,
                        const float* __restrict__ wy1, const float* __restrict__ by1,
                        const float* __restrict__ wy0, const float* __restrict__ by0,
                        float* __restrict__ out) {
    int i = blockIdx.x * 8 + (threadIdx.x >> 5);
    if (i >= 40000) return;
    int lane = threadIdx.x & 31;
    int idx = (i < 20000) ? tidx[i] : cidx[i - 20000];
    float4 z  = *(const float4*)&Z[idx * DIM + lane * 4];
    float4 w1 = *(const float4*)&wy1[lane * 4];
    float4 w0 = *(const float4*)&wy0[lane * 4];
    float d1 = z.x * w1.x + z.y * w1.y + z.z * w1.z + z.w * w1.w;
    float d0 = z.x * w0.x + z.y * w0.y + z.z * w0.z + z.w * w0.w;
    #pragma unroll
    for (int d = 16; d; d >>= 1) {
        d1 += __shfl_xor_sync(0xffffffffu, d1, d);
        d0 += __shfl_xor_sync(0xffffffffu, d0, d);
    }
    if (lane == 0) {
        float v1 = d1 + by1[0]; v1 = (v1 > 0.f) ? v1 : 0.01f * v1;
        float v0 = d0 + by0[0]; v0 = (v0 > 0.f) ? v0 : 0.01f * v0;
        if (i < 20000) { out[i] = v1; out[20000 + i] = v0; }
        else { int j = i - 20000; out[40000 + j] = v0; out[60000 + j] = v1; }
    }
}

// ---------------- launch -------------------------------------------------------
extern "C" void kernel_launch(void* const* d_in, const int* in_sizes, int n_in,
                              void* d_out, int out_size) {
    const float* x   = (const float*)d_in[0];
    const int*   ei  = (const int*)  d_in[1];
    const int*   ti  = (const int*)  d_in[2];
    const int*   ci  = (const int*)  d_in[3];
    const float* W1  = (const float*)d_in[4];
    const float* as1 = (const float*)d_in[5];
    const float* ad1 = (const float*)d_in[6];
    const float* b1  = (const float*)d_in[7];
    const float* W2  = (const float*)d_in[8];
    const float* as2 = (const float*)d_in[9];
    const float* ad2 = (const float*)d_in[10];
    const float* b2  = (const float*)d_in[11];
    const float* wy1 = (const float*)d_in[12];
    const float* by1 = (const float*)d_in[13];
    const float* wy0 = (const float*)d_in[14];
    const float* by0 = (const float*)d_in[15];
    float* out = (float*)d_out;
    float* xZ2 = out + 80000;

    void *ph, *px1;
    cudaGetSymbolAddress(&ph,  g_h);
    cudaGetSymbolAddress(&px1, g_x1);
    float* h  = (float*)ph;
    float* x1 = (float*)px1;

    // one-time side stream + fork/join events (created on the uncaptured
    // correctness call; reused by every captured replay)
    static cudaStream_t s_side = nullptr;
    static cudaEvent_t  ev_fork = nullptr, ev_join = nullptr;
    if (!s_side) {
        cudaStreamCreateWithFlags(&s_side, cudaStreamNonBlocking);
        cudaEventCreateWithFlags(&ev_fork, cudaEventDisableTiming);
        cudaEventCreateWithFlags(&ev_join, cudaEventDisableTiming);
    }

    const int smem = (3 * 128 * LDSP + 256) * (int)sizeof(float);   // 209920 B
    cudaFuncSetAttribute(k_gemm, cudaFuncAttributeMaxDynamicSharedMemorySize, smem);

    // fork: CSR build on side stream, concurrent with layer-1 GEMM
    cudaEventRecord(ev_fork, 0);
    cudaStreamWaitEvent(s_side, ev_fork, 0);
    k_hist   <<<(NE / 4 + 255) / 256, 256, 0, s_side>>>(ei);
    k_scan1  <<<NPAD / 1024, 1024, 0, s_side>>>();
    k_scan3f <<<NPAD / 1024, 1024, 0, s_side>>>();
    k_scatter<<<(NE / 4 + 255) / 256, 256, 0, s_side>>>(ei);
    k_sortseg<<<(NN + 7) / 8, 256, 0, s_side>>>();
    cudaEventRecord(ev_join, s_side);

    // main stream: layer-1 GEMM (independent of CSR)
    k_gemm<<<(NN + 127) / 128, 256, smem>>>(x, W1, h, NN, as1, ad1);

    // join: aggregation needs both CSR and H/logits
    cudaStreamWaitEvent(0, ev_join, 0);
    k_agg<<<(NN + 7) / 8, 256>>>(h, b1, x1, 1);

    // layer 2 (output straight into d_out's xZ2 region)
    k_gemm<<<(NN + 127) / 128, 256, smem>>>(x1, W2, h, NN, as2, ad2);
    k_agg<<<(NN + 7) / 8, 256>>>(h, b2, xZ2, 0);

    // heads
    k_heads<<<(40000 + 7) / 8, 256>>>(xZ2, ti, ci, wy1, by1, wy0, by0, out);
}